// round 1
// baseline (speedup 1.0000x reference)
#include <cuda_runtime.h>

#define Bq 32
#define Sq 48
#define Lq 64
#define Fq 256

// ---------- packed f32x2 helpers ----------
__device__ __forceinline__ unsigned long long pk2(float lo, float hi) {
    unsigned long long r;
    asm("mov.b64 %0, {%1, %2};" : "=l"(r) : "f"(lo), "f"(hi));
    return r;
}
__device__ __forceinline__ void up2(unsigned long long v, float& lo, float& hi) {
    asm("mov.b64 {%0, %1}, %2;" : "=f"(lo), "=f"(hi) : "l"(v));
}
__device__ __forceinline__ unsigned long long fma2(unsigned long long a,
                                                   unsigned long long b,
                                                   unsigned long long c) {
    unsigned long long d;
    asm("fma.rn.f32x2 %0, %1, %2, %3;" : "=l"(d) : "l"(a), "l"(b), "l"(c));
    return d;
}

// SMEM layout (floats):
//   Xs  : 64*256   = 16384
//   Ws  : 128*256  = 32768   (W1 K-chunk)
//   invd: 64, scores: 64, wgt: 64
static constexpr int SMEM_FLOATS = 16384 + 32768 + 64 + 64 + 64;

__global__ __launch_bounds__(256, 1)
void ida_fused_kernel(const float* __restrict__ features,
                      const float* __restrict__ src_locs,
                      const float* __restrict__ tar_locs,
                      const float* __restrict__ W1,
                      const float* __restrict__ b1,
                      const float* __restrict__ W2,
                      const float* __restrict__ b2,
                      float* __restrict__ out)
{
    extern __shared__ float sm[];
    float* Xs     = sm;                    // 16384
    float* Ws     = sm + 16384;            // 32768
    float* invd   = sm + 16384 + 32768;    // 64
    float* scores = invd + 64;             // 64
    float* wgt    = scores + 64;           // 64

    const int bs = blockIdx.x;            // b*S + s
    const int b  = bs / Sq;
    const int t  = threadIdx.x;
    const int tx = t & 31;                // 0..31 -> g columns
    const int ty = t >> 5;                // 0..7  -> l rows (8 per thread)

    // ---- Phase 1: load X = features[b][s][:][:] (contiguous 64KB) ----
    {
        const float4* gx = reinterpret_cast<const float4*>(features + (size_t)bs * (Lq * Fq));
        float4* sx4 = reinterpret_cast<float4*>(Xs);
        #pragma unroll
        for (int i = 0; i < 16; ++i) sx4[t + i * 256] = gx[t + i * 256];
    }
    if (t < Lq) {
        float dx = src_locs[(b * Lq + t) * 2 + 0] - tar_locs[b * 2 + 0];
        float dy = src_locs[(b * Lq + t) * 2 + 1] - tar_locs[b * 2 + 1];
        invd[t] = rsqrtf(dx * dx + dy * dy);
    }

    // Thread owns g columns: group A = [4*tx .. 4*tx+3], group B = [128+4*tx .. +3]
    const int gA = tx * 4;
    const int gB = 128 + tx * 4;

    // acc[i][j]: i = l row (ty*8 + i), j: 0,1 -> group A pairs; 2,3 -> group B pairs
    unsigned long long acc[8][4];
    {
        unsigned long long p0 = pk2(b1[gA],     b1[gA + 1]);
        unsigned long long p1 = pk2(b1[gA + 2], b1[gA + 3]);
        unsigned long long p2 = pk2(b1[gB],     b1[gB + 1]);
        unsigned long long p3 = pk2(b1[gB + 2], b1[gB + 3]);
        #pragma unroll
        for (int i = 0; i < 8; ++i) {
            acc[i][0] = p0; acc[i][1] = p1; acc[i][2] = p2; acc[i][3] = p3;
        }
    }

    // ---- Phase 2: h = relu(X @ W1 + b1), kept in registers ----
    for (int fc = 0; fc < 2; ++fc) {
        __syncthreads();
        {   // stage W1 rows [fc*128, fc*128+128) x 256 into SMEM
            const float4* gw = reinterpret_cast<const float4*>(W1 + (size_t)fc * 128 * 256);
            float4* sw4 = reinterpret_cast<float4*>(Ws);
            #pragma unroll
            for (int i = 0; i < 32; ++i) sw4[t + i * 256] = gw[t + i * 256];
        }
        __syncthreads();

        const float* xbase = Xs + (ty * 8) * Fq + fc * 128;
        #pragma unroll 1
        for (int fr = 0; fr < 128; fr += 4) {
            float4 xr[8];
            #pragma unroll
            for (int i = 0; i < 8; ++i)
                xr[i] = *reinterpret_cast<const float4*>(xbase + i * Fq + fr);

            #pragma unroll
            for (int u = 0; u < 4; ++u) {
                const float* wrow = Ws + (fr + u) * 256;
                ulonglong2 wa = *reinterpret_cast<const ulonglong2*>(wrow + gA);
                ulonglong2 wb = *reinterpret_cast<const ulonglong2*>(wrow + gB);
                #pragma unroll
                for (int i = 0; i < 8; ++i) {
                    const float* xp = reinterpret_cast<const float*>(&xr[i]);
                    float xv = xp[u];
                    unsigned long long xx = pk2(xv, xv);
                    acc[i][0] = fma2(xx, wa.x, acc[i][0]);
                    acc[i][1] = fma2(xx, wa.y, acc[i][1]);
                    acc[i][2] = fma2(xx, wb.x, acc[i][2]);
                    acc[i][3] = fma2(xx, wb.y, acc[i][3]);
                }
            }
        }
    }

    // ---- Phase 3: score[l] = relu( sum_g relu(h[l,g])*W2[g] + b2 ) * invd[l] ----
    {
        float w2[8];
        w2[0] = W2[gA]; w2[1] = W2[gA + 1]; w2[2] = W2[gA + 2]; w2[3] = W2[gA + 3];
        w2[4] = W2[gB]; w2[5] = W2[gB + 1]; w2[6] = W2[gB + 2]; w2[7] = W2[gB + 3];
        const float b2v = b2[0];

        #pragma unroll
        for (int i = 0; i < 8; ++i) {
            float p = 0.f;
            #pragma unroll
            for (int j = 0; j < 4; ++j) {
                float lo, hi;
                up2(acc[i][j], lo, hi);
                p = fmaf(fmaxf(lo, 0.f), w2[j * 2 + 0], p);
                p = fmaf(fmaxf(hi, 0.f), w2[j * 2 + 1], p);
            }
            #pragma unroll
            for (int off = 16; off > 0; off >>= 1)
                p += __shfl_xor_sync(0xffffffffu, p, off);
            if (tx == 0) {
                int l = ty * 8 + i;
                float h2 = fmaxf(p + b2v, 0.f);
                scores[l] = h2 * invd[l];
            }
        }
    }
    __syncthreads();

    // ---- Phase 4: softmax over l (warp 0) ----
    if (ty == 0) {
        float s0 = scores[tx];
        float s1 = scores[tx + 32];
        float m = fmaxf(s0, s1);
        #pragma unroll
        for (int off = 16; off > 0; off >>= 1)
            m = fmaxf(m, __shfl_xor_sync(0xffffffffu, m, off));
        float e0 = expf(s0 - m);
        float e1 = expf(s1 - m);
        float ssum = e0 + e1;
        #pragma unroll
        for (int off = 16; off > 0; off >>= 1)
            ssum += __shfl_xor_sync(0xffffffffu, ssum, off);
        float inv = 1.f / ssum;
        wgt[tx]      = e0 * inv;
        wgt[tx + 32] = e1 * inv;
    }
    __syncthreads();

    // ---- Phase 5: out[b,s,f] = sum_l wgt[l] * X[l,f]  (X reused from SMEM) ----
    {
        float o = 0.f;
        #pragma unroll
        for (int l = 0; l < Lq; ++l)
            o = fmaf(wgt[l], Xs[l * Fq + t], o);
        out[(size_t)bs * Fq + t] = o;
    }
}

extern "C" void kernel_launch(void* const* d_in, const int* in_sizes, int n_in,
                              void* d_out, int out_size)
{
    const float* features = (const float*)d_in[0];
    const float* src_locs = (const float*)d_in[1];
    const float* tar_locs = (const float*)d_in[2];
    const float* W1       = (const float*)d_in[3];
    const float* b1       = (const float*)d_in[4];
    const float* W2       = (const float*)d_in[5];
    const float* b2       = (const float*)d_in[6];
    float* out            = (float*)d_out;

    const size_t smem_bytes = SMEM_FLOATS * sizeof(float);   // 197376 B
    cudaFuncSetAttribute(ida_fused_kernel,
                         cudaFuncAttributeMaxDynamicSharedMemorySize,
                         (int)smem_bytes);

    ida_fused_kernel<<<Bq * Sq, 256, smem_bytes>>>(
        features, src_locs, tar_locs, W1, b1, W2, b2, out);
}

// round 4
// speedup vs baseline: 1.4413x; 1.4413x over previous
#include <cuda_runtime.h>
#include <cuda_bf16.h>
#include <mma.h>
#include <cstdint>

using namespace nvcuda;

#define Bq 32
#define Sq 48
#define Lq 64
#define Fq 256

// ---------------- staged W1: bf16 hi/lo, [k][n] row-major, 128KB each ----------------
__device__ __align__(16) __nv_bfloat16 g_Whi[256 * 256];
__device__ __align__(16) __nv_bfloat16 g_Wlo[256 * 256];

__global__ void stage_w1_kernel(const float* __restrict__ W1) {
    int idx = blockIdx.x * 256 + threadIdx.x;   // 65536 = [k][n]
    float v = W1[idx];
    __nv_bfloat16 hi = __float2bfloat16_rn(v);
    __nv_bfloat16 lo = __float2bfloat16_rn(v - __bfloat162float(hi));
    g_Whi[idx] = hi;
    g_Wlo[idx] = lo;
}

// ---------------- cp.async helpers ----------------
__device__ __forceinline__ uint32_t smem_u32(const void* p) {
    uint32_t a;
    asm("{ .reg .u64 t; cvta.to.shared.u64 t, %1; cvt.u32.u64 %0, t; }" : "=r"(a) : "l"(p));
    return a;
}
__device__ __forceinline__ void cp16(uint32_t dst, const void* src) {
    asm volatile("cp.async.ca.shared.global [%0], [%1], 16;" :: "r"(dst), "l"(src));
}
#define CP_COMMIT() asm volatile("cp.async.commit_group;" ::: "memory")
#define CP_WAIT0()  asm volatile("cp.async.wait_group 0;" ::: "memory")

// ---------------- SMEM layout (bytes) ----------------
// X tiles: [128][264] bf16, hi + lo
static constexpr int XLD     = 264;
static constexpr int XHI_OFF = 0;                       // 128*264*2 = 67584
static constexpr int XLO_OFF = 67584;                   // 67584
// W double buffer: 2 bufs x 2 comps x [32][264] bf16 (comp stride 16896, buf 33792)
static constexpr int WB_OFF  = 135168;                  // 67584
// hbuf (epilogue, reuses WB region): [128 cols][132] f32 = 67584
static constexpr int HLD     = 132;
// aux
static constexpr int W2B1_OFF = 202752;                 // float2[256] = 2048
static constexpr int INVD_OFF = 204800;                 // float[64]
static constexpr int SC_OFF   = 205056;                 // float[128]
static constexpr int WGT_OFF  = 205568;                 // float[128]
static constexpr int PRED_OFF = 206080;                 // float[256] = 1024
static constexpr int SMEM_BYTES = 207104;

__global__ __launch_bounds__(256, 1)
void ida_wmma_kernel(const float* __restrict__ features,
                     const float* __restrict__ src_locs,
                     const float* __restrict__ tar_locs,
                     const float* __restrict__ b1,
                     const float* __restrict__ W2,
                     const float* __restrict__ b2,
                     float* __restrict__ out)
{
    extern __shared__ char smem[];
    const uint32_t sb = smem_u32(smem);
    const int t      = threadIdx.x;
    const int wid    = t >> 5;
    const int warp_m = wid & 3;        // 0..3 -> rows [warp_m*32, +32)
    const int warp_n = wid >> 2;       // 0..1 -> cols [warp_n*128, +128)
    const int bs0    = blockIdx.x * 2;
    const int b      = bs0 / Sq;

    __nv_bfloat16* Xhi = reinterpret_cast<__nv_bfloat16*>(smem + XHI_OFF);
    __nv_bfloat16* Xlo = reinterpret_cast<__nv_bfloat16*>(smem + XLO_OFF);

    // ---- prologue: async-load W chunk 0 into buf 0 ----
    {
        // 2048 16B segs: seg = comp*1024 + row*32 + s ; 8 per thread
        #pragma unroll
        for (int j = 0; j < 8; ++j) {
            int seg  = t + j * 256;
            int comp = seg >> 10;
            int row  = (seg >> 5) & 31;
            int s    = seg & 31;
            const __nv_bfloat16* src = (comp ? g_Wlo : g_Whi) + row * 256 + s * 8;
            uint32_t dst = sb + WB_OFF + comp * 16896 + row * 528 + s * 16;
            cp16(dst, src);
        }
        CP_COMMIT();
    }

    // ---- load X (128 x 256 f32, contiguous 128KB), split to bf16 hi/lo ----
    {
        const float4* gx = reinterpret_cast<const float4*>(features + (size_t)bs0 * (Lq * Fq));
        #pragma unroll
        for (int r = 0; r < 32; ++r) {
            int idx = t + r * 256;          // = m*64 + q
            int m = idx >> 6, q = idx & 63;
            float4 x = gx[idx];
            __nv_bfloat16 h0 = __float2bfloat16_rn(x.x);
            __nv_bfloat16 h1 = __float2bfloat16_rn(x.y);
            __nv_bfloat16 h2 = __float2bfloat16_rn(x.z);
            __nv_bfloat16 h3 = __float2bfloat16_rn(x.w);
            __nv_bfloat16 l0 = __float2bfloat16_rn(x.x - __bfloat162float(h0));
            __nv_bfloat16 l1 = __float2bfloat16_rn(x.y - __bfloat162float(h1));
            __nv_bfloat16 l2 = __float2bfloat16_rn(x.z - __bfloat162float(h2));
            __nv_bfloat16 l3 = __float2bfloat16_rn(x.w - __bfloat162float(h3));
            uint2 hp, lp;
            hp.x = ((uint32_t)__bfloat16_as_ushort(h1) << 16) | __bfloat16_as_ushort(h0);
            hp.y = ((uint32_t)__bfloat16_as_ushort(h3) << 16) | __bfloat16_as_ushort(h2);
            lp.x = ((uint32_t)__bfloat16_as_ushort(l1) << 16) | __bfloat16_as_ushort(l0);
            lp.y = ((uint32_t)__bfloat16_as_ushort(l3) << 16) | __bfloat16_as_ushort(l2);
            *reinterpret_cast<uint2*>(reinterpret_cast<char*>(Xhi) + m * 528 + q * 8) = hp;
            *reinterpret_cast<uint2*>(reinterpret_cast<char*>(Xlo) + m * 528 + q * 8) = lp;
        }
    }
    // aux
    {
        float2* wb = reinterpret_cast<float2*>(smem + W2B1_OFF);
        wb[t] = make_float2(b1[t], W2[t]);
        if (t < Lq) {
            float dx = src_locs[(b * Lq + t) * 2 + 0] - tar_locs[b * 2 + 0];
            float dy = src_locs[(b * Lq + t) * 2 + 1] - tar_locs[b * 2 + 1];
            reinterpret_cast<float*>(smem + INVD_OFF)[t] = rsqrtf(dx * dx + dy * dy);
        }
    }
    CP_WAIT0();
    __syncthreads();

    // ---- wmma mainloop: 8 K-chunks of 32, double buffered ----
    wmma::fragment<wmma::accumulator, 16, 16, 16, float> acc[2][8];
    #pragma unroll
    for (int mt = 0; mt < 2; ++mt)
        #pragma unroll
        for (int nt = 0; nt < 8; ++nt)
            wmma::fill_fragment(acc[mt][nt], 0.f);

    #pragma unroll 1
    for (int c = 0; c < 8; ++c) {
        if (c < 7) {   // prefetch next chunk into other buffer
            int nb = (c + 1) & 1;
            #pragma unroll
            for (int j = 0; j < 8; ++j) {
                int seg  = t + j * 256;
                int comp = seg >> 10;
                int row  = (seg >> 5) & 31;
                int s    = seg & 31;
                const __nv_bfloat16* src =
                    (comp ? g_Wlo : g_Whi) + ((c + 1) * 32 + row) * 256 + s * 8;
                uint32_t dst = sb + WB_OFF + nb * 33792 + comp * 16896 + row * 528 + s * 16;
                cp16(dst, src);
            }
            CP_COMMIT();
        }

        const __nv_bfloat16* Wh =
            reinterpret_cast<const __nv_bfloat16*>(smem + WB_OFF + (c & 1) * 33792);
        const __nv_bfloat16* Wl =
            reinterpret_cast<const __nv_bfloat16*>(smem + WB_OFF + (c & 1) * 33792 + 16896);

        #pragma unroll
        for (int ks = 0; ks < 2; ++ks) {
            const int kg = c * 32 + ks * 16;      // global k for A
            const int kl = ks * 16;               // local k row in W buf
            wmma::fragment<wmma::matrix_a, 16, 16, 16, __nv_bfloat16, wmma::row_major> ah[2], al[2];
            #pragma unroll
            for (int mt = 0; mt < 2; ++mt) {
                int row = warp_m * 32 + mt * 16;
                wmma::load_matrix_sync(ah[mt], Xhi + row * XLD + kg, XLD);
                wmma::load_matrix_sync(al[mt], Xlo + row * XLD + kg, XLD);
            }
            #pragma unroll
            for (int nt = 0; nt < 8; ++nt) {
                int col = warp_n * 128 + nt * 16;
                wmma::fragment<wmma::matrix_b, 16, 16, 16, __nv_bfloat16, wmma::row_major> bh, bl;
                wmma::load_matrix_sync(bh, Wh + kl * XLD + col, XLD);
                wmma::load_matrix_sync(bl, Wl + kl * XLD + col, XLD);
                #pragma unroll
                for (int mt = 0; mt < 2; ++mt) {
                    wmma::mma_sync(acc[mt][nt], ah[mt], bh, acc[mt][nt]);
                    wmma::mma_sync(acc[mt][nt], al[mt], bh, acc[mt][nt]);
                    wmma::mma_sync(acc[mt][nt], ah[mt], bl, acc[mt][nt]);
                }
            }
        }
        if (c < 7) { CP_WAIT0(); }
        __syncthreads();
    }

    // ---- epilogue: h=relu(D+b1); p=h.W2 per row; two N-halves through hbuf ----
    float* hbuf = reinterpret_cast<float*>(smem + WB_OFF);
    const float2* wb = reinterpret_cast<const float2*>(smem + W2B1_OFF);
    float p = 0.f;
    {
        const int r  = t & 127;
        const int cs = (t >> 7) * 64;
        #pragma unroll 1
        for (int half = 0; half < 2; ++half) {
            if (warp_n == half) {
                #pragma unroll
                for (int mt = 0; mt < 2; ++mt)
                    #pragma unroll
                    for (int nt = 0; nt < 8; ++nt)
                        wmma::store_matrix_sync(
                            hbuf + (nt * 16) * HLD + warp_m * 32 + mt * 16,
                            acc[mt][nt], HLD, wmma::mem_col_major);
            }
            __syncthreads();
            #pragma unroll 4
            for (int j = 0; j < 64; ++j) {
                int colg = half * 128 + cs + j;
                float2 c2 = wb[colg];
                float v = hbuf[(cs + j) * HLD + r] + c2.x;
                p = fmaf(fmaxf(v, 0.f), c2.y, p);
            }
            __syncthreads();
        }
    }
    // combine the two column-subsets, score
    {
        float* pred = reinterpret_cast<float*>(smem + PRED_OFF);
        pred[t] = p;
        __syncthreads();
        if (t < 128) {
            float ptot = pred[t] + pred[t + 128];
            float s = fmaxf(ptot + b2[0], 0.f) *
                      reinterpret_cast<const float*>(smem + INVD_OFF)[t & 63];
            reinterpret_cast<float*>(smem + SC_OFF)[t] = s;
        }
    }
    __syncthreads();

    // ---- softmax over L=64 per s-tile (warps 0,1) ----
    if (wid < 2) {
        const float* sc = reinterpret_cast<const float*>(smem + SC_OFF) + wid * 64;
        float* wg = reinterpret_cast<float*>(smem + WGT_OFF) + wid * 64;
        int lane = t & 31;
        float s0 = sc[lane], s1 = sc[lane + 32];
        float m = fmaxf(s0, s1);
        #pragma unroll
        for (int off = 16; off > 0; off >>= 1)
            m = fmaxf(m, __shfl_xor_sync(0xffffffffu, m, off));
        float e0 = expf(s0 - m), e1 = expf(s1 - m);
        float ssum = e0 + e1;
        #pragma unroll
        for (int off = 16; off > 0; off >>= 1)
            ssum += __shfl_xor_sync(0xffffffffu, ssum, off);
        float inv = 1.f / ssum;
        wg[lane] = e0 * inv;
        wg[lane + 32] = e1 * inv;
    }
    __syncthreads();

    // ---- phase 5: out = sum_l wgt[l] * (Xhi+Xlo)[l,f] ----
    {
        const float* wg = reinterpret_cast<const float*>(smem + WGT_OFF);
        float o0 = 0.f, o1 = 0.f;
        #pragma unroll 8
        for (int l = 0; l < 64; ++l) {
            float x0 = __bfloat162float(Xhi[l * XLD + t]) +
                       __bfloat162float(Xlo[l * XLD + t]);
            float x1 = __bfloat162float(Xhi[(l + 64) * XLD + t]) +
                       __bfloat162float(Xlo[(l + 64) * XLD + t]);
            o0 = fmaf(wg[l], x0, o0);
            o1 = fmaf(wg[l + 64], x1, o1);
        }
        out[(size_t)bs0 * Fq + t] = o0;
        out[(size_t)(bs0 + 1) * Fq + t] = o1;
    }
}

extern "C" void kernel_launch(void* const* d_in, const int* in_sizes, int n_in,
                              void* d_out, int out_size)
{
    const float* features = (const float*)d_in[0];
    const float* src_locs = (const float*)d_in[1];
    const float* tar_locs = (const float*)d_in[2];
    const float* W1       = (const float*)d_in[3];
    const float* b1       = (const float*)d_in[4];
    const float* W2       = (const float*)d_in[5];
    const float* b2       = (const float*)d_in[6];
    float* out            = (float*)d_out;

    stage_w1_kernel<<<256, 256>>>(W1);

    cudaFuncSetAttribute(ida_wmma_kernel,
                         cudaFuncAttributeMaxDynamicSharedMemorySize, SMEM_BYTES);
    ida_wmma_kernel<<<(Bq * Sq) / 2, 256, SMEM_BYTES>>>(
        features, src_locs, tar_locs, b1, W2, b2, out);
}

// round 6
// speedup vs baseline: 1.5850x; 1.0997x over previous
#include <cuda_runtime.h>
#include <cuda_bf16.h>
#include <mma.h>
#include <cstdint>

using namespace nvcuda;

#define Bq 32
#define Sq 48
#define Lq 64
#define Fq 256

// ---------------- staged W1: bf16 hi/lo, [k][n] row-major, 128KB each ----------------
__device__ __align__(16) __nv_bfloat16 g_Whi[256 * 256];
__device__ __align__(16) __nv_bfloat16 g_Wlo[256 * 256];

__global__ void stage_w1_kernel(const float* __restrict__ W1) {
    int idx = blockIdx.x * 256 + threadIdx.x;   // 65536 = [k][n]
    float v = W1[idx];
    __nv_bfloat16 hi = __float2bfloat16_rn(v);
    __nv_bfloat16 lo = __float2bfloat16_rn(v - __bfloat162float(hi));
    g_Whi[idx] = hi;
    g_Wlo[idx] = lo;
}

// ---------------- cp.async helpers ----------------
__device__ __forceinline__ uint32_t smem_u32(const void* p) {
    uint32_t a;
    asm("{ .reg .u64 t; cvta.to.shared.u64 t, %1; cvt.u32.u64 %0, t; }" : "=r"(a) : "l"(p));
    return a;
}
__device__ __forceinline__ void cp16(uint32_t dst, const void* src) {
    asm volatile("cp.async.ca.shared.global [%0], [%1], 16;" :: "r"(dst), "l"(src));
}
#define CP_COMMIT() asm volatile("cp.async.commit_group;" ::: "memory")
#define CP_WAIT0()  asm volatile("cp.async.wait_group 0;" ::: "memory")

// ---------------- SMEM layout (bytes), M=64 CTA ----------------
static constexpr int XLD     = 264;                 // bf16 elems per X row
static constexpr int XHI_OFF = 0;                   // 64*264*2 = 33792
static constexpr int XLO_OFF = 33792;               // 33792
// W double buffer: 2 bufs x 2 comps x [16 rows][264] bf16 (comp 8448, buf 16896)
static constexpr int WB_OFF  = 67584;               // 33792 total
// hbuf (epilogue, aliases WB region): [128 cols][66] f32 = 33792
static constexpr int HLD     = 66;
static constexpr int W2B1_OFF = 101376;             // float2[256] = 2048
static constexpr int INVD_OFF = 103424;             // float[64]
static constexpr int SC_OFF   = 103680;             // float[64]
static constexpr int WGT_OFF  = 103936;             // float[64]
static constexpr int PRED_OFF = 104192;             // float[256]
static constexpr int SMEM_BYTES = 105216;

__global__ __launch_bounds__(256, 2)
void ida_wmma_kernel(const float* __restrict__ features,
                     const float* __restrict__ src_locs,
                     const float* __restrict__ tar_locs,
                     const float* __restrict__ b1,
                     const float* __restrict__ W2,
                     const float* __restrict__ b2,
                     float* __restrict__ out)
{
    extern __shared__ char smem[];
    const uint32_t sb = smem_u32(smem);
    const int t      = threadIdx.x;
    const int wid    = t >> 5;
    const int warp_m = wid & 1;        // rows [warp_m*32, +32)
    const int warp_n = wid >> 1;       // cols [warp_n*64, +64)
    const int bs     = blockIdx.x;     // one (b,s) tile
    const int b      = bs / Sq;

    __nv_bfloat16* Xhi = reinterpret_cast<__nv_bfloat16*>(smem + XHI_OFF);
    __nv_bfloat16* Xlo = reinterpret_cast<__nv_bfloat16*>(smem + XLO_OFF);

    // ---- prologue: async-load W kstep 0 into buf 0 ----
    {
        // 1024 16B segs: seg = comp*512 + row*32 + s16 ; 4 per thread
        #pragma unroll
        for (int j = 0; j < 4; ++j) {
            int seg  = t + j * 256;
            int comp = seg >> 9;
            int row  = (seg >> 5) & 15;
            int s16  = seg & 31;
            const __nv_bfloat16* src = (comp ? g_Wlo : g_Whi) + row * 256 + s16 * 8;
            uint32_t dst = sb + WB_OFF + comp * 8448 + row * 528 + s16 * 16;
            cp16(dst, src);
        }
        CP_COMMIT();
    }

    // ---- load X (64 x 256 f32, contiguous 64KB), split to bf16 hi/lo ----
    {
        const float4* gx = reinterpret_cast<const float4*>(features + (size_t)bs * (Lq * Fq));
        #pragma unroll
        for (int r = 0; r < 16; ++r) {
            int idx = t + r * 256;          // = m*64 + q
            int m = idx >> 6, q = idx & 63;
            float4 x = gx[idx];
            __nv_bfloat16 h0 = __float2bfloat16_rn(x.x);
            __nv_bfloat16 h1 = __float2bfloat16_rn(x.y);
            __nv_bfloat16 h2 = __float2bfloat16_rn(x.z);
            __nv_bfloat16 h3 = __float2bfloat16_rn(x.w);
            __nv_bfloat16 l0 = __float2bfloat16_rn(x.x - __bfloat162float(h0));
            __nv_bfloat16 l1 = __float2bfloat16_rn(x.y - __bfloat162float(h1));
            __nv_bfloat16 l2 = __float2bfloat16_rn(x.z - __bfloat162float(h2));
            __nv_bfloat16 l3 = __float2bfloat16_rn(x.w - __bfloat162float(h3));
            uint2 hp, lp;
            hp.x = ((uint32_t)__bfloat16_as_ushort(h1) << 16) | __bfloat16_as_ushort(h0);
            hp.y = ((uint32_t)__bfloat16_as_ushort(h3) << 16) | __bfloat16_as_ushort(h2);
            lp.x = ((uint32_t)__bfloat16_as_ushort(l1) << 16) | __bfloat16_as_ushort(l0);
            lp.y = ((uint32_t)__bfloat16_as_ushort(l3) << 16) | __bfloat16_as_ushort(l2);
            *reinterpret_cast<uint2*>(reinterpret_cast<char*>(Xhi) + m * 528 + q * 8) = hp;
            *reinterpret_cast<uint2*>(reinterpret_cast<char*>(Xlo) + m * 528 + q * 8) = lp;
        }
    }
    // aux
    {
        float2* wb = reinterpret_cast<float2*>(smem + W2B1_OFF);
        wb[t] = make_float2(b1[t], W2[t]);
        if (t < Lq) {
            float dx = src_locs[(b * Lq + t) * 2 + 0] - tar_locs[b * 2 + 0];
            float dy = src_locs[(b * Lq + t) * 2 + 1] - tar_locs[b * 2 + 1];
            reinterpret_cast<float*>(smem + INVD_OFF)[t] = rsqrtf(dx * dx + dy * dy);
        }
    }
    CP_WAIT0();
    __syncthreads();

    // ---- wmma mainloop: 16 K-steps of 16, double buffered ----
    wmma::fragment<wmma::accumulator, 16, 16, 16, float> acc[2][4];
    #pragma unroll
    for (int mt = 0; mt < 2; ++mt)
        #pragma unroll
        for (int nt = 0; nt < 4; ++nt)
            wmma::fill_fragment(acc[mt][nt], 0.f);

    #pragma unroll 1
    for (int s = 0; s < 16; ++s) {
        if (s < 15) {   // prefetch next kstep into other buffer
            int nb = (s + 1) & 1;
            #pragma unroll
            for (int j = 0; j < 4; ++j) {
                int seg  = t + j * 256;
                int comp = seg >> 9;
                int row  = (seg >> 5) & 15;
                int s16  = seg & 31;
                const __nv_bfloat16* src =
                    (comp ? g_Wlo : g_Whi) + ((s + 1) * 16 + row) * 256 + s16 * 8;
                uint32_t dst = sb + WB_OFF + nb * 16896 + comp * 8448 + row * 528 + s16 * 16;
                cp16(dst, src);
            }
            CP_COMMIT();
        }

        const __nv_bfloat16* Wh =
            reinterpret_cast<const __nv_bfloat16*>(smem + WB_OFF + (s & 1) * 16896);
        const __nv_bfloat16* Wl =
            reinterpret_cast<const __nv_bfloat16*>(smem + WB_OFF + (s & 1) * 16896 + 8448);

        const int kg = s * 16;
        wmma::fragment<wmma::matrix_a, 16, 16, 16, __nv_bfloat16, wmma::row_major> ah[2], al[2];
        #pragma unroll
        for (int mt = 0; mt < 2; ++mt) {
            int row = warp_m * 32 + mt * 16;
            wmma::load_matrix_sync(ah[mt], Xhi + row * XLD + kg, XLD);
            wmma::load_matrix_sync(al[mt], Xlo + row * XLD + kg, XLD);
        }
        #pragma unroll
        for (int nt = 0; nt < 4; ++nt) {
            int col = warp_n * 64 + nt * 16;
            wmma::fragment<wmma::matrix_b, 16, 16, 16, __nv_bfloat16, wmma::row_major> bh, bl;
            wmma::load_matrix_sync(bh, Wh + col, XLD);
            wmma::load_matrix_sync(bl, Wl + col, XLD);
            #pragma unroll
            for (int mt = 0; mt < 2; ++mt) {
                wmma::mma_sync(acc[mt][nt], ah[mt], bh, acc[mt][nt]);
                wmma::mma_sync(acc[mt][nt], al[mt], bh, acc[mt][nt]);
                wmma::mma_sync(acc[mt][nt], ah[mt], bl, acc[mt][nt]);
            }
        }
        if (s < 15) { CP_WAIT0(); }
        __syncthreads();
    }

    // ---- epilogue: h=relu(D+b1); p=h.W2 per row; two 128-col halves via hbuf ----
    float* hbuf = reinterpret_cast<float*>(smem + WB_OFF);
    const float2* wb = reinterpret_cast<const float2*>(smem + W2B1_OFF);
    float p = 0.f;
    {
        const int r    = t & 63;
        const int cseg = t >> 6;            // 0..3 -> 32 cols each within a half
        #pragma unroll 1
        for (int half = 0; half < 2; ++half) {
            if ((warp_n >> 1) == half) {
                int colbase = (warp_n & 1) * 64;
                #pragma unroll
                for (int mt = 0; mt < 2; ++mt)
                    #pragma unroll
                    for (int nt = 0; nt < 4; ++nt)
                        wmma::store_matrix_sync(
                            hbuf + (colbase + nt * 16) * HLD + warp_m * 32 + mt * 16,
                            acc[mt][nt], HLD, wmma::mem_col_major);
            }
            __syncthreads();
            #pragma unroll 4
            for (int j = 0; j < 32; ++j) {
                int lc = cseg * 32 + j;
                float2 c2 = wb[half * 128 + lc];
                float v = hbuf[lc * HLD + r] + c2.x;
                p = fmaf(fmaxf(v, 0.f), c2.y, p);
            }
            __syncthreads();
        }
    }
    // combine 4 column-subsets per row, score
    {
        float* pred = reinterpret_cast<float*>(smem + PRED_OFF);
        pred[t] = p;
        __syncthreads();
        if (t < 64) {
            float ptot = pred[t] + pred[t + 64] + pred[t + 128] + pred[t + 192];
            float sscore = fmaxf(ptot + b2[0], 0.f) *
                           reinterpret_cast<const float*>(smem + INVD_OFF)[t];
            reinterpret_cast<float*>(smem + SC_OFF)[t] = sscore;
        }
    }
    __syncthreads();

    // ---- softmax over L=64 (warp 0) ----
    if (wid == 0) {
        const float* sc = reinterpret_cast<const float*>(smem + SC_OFF);
        float* wg = reinterpret_cast<float*>(smem + WGT_OFF);
        int lane = t & 31;
        float s0 = sc[lane], s1 = sc[lane + 32];
        float m = fmaxf(s0, s1);
        #pragma unroll
        for (int off = 16; off > 0; off >>= 1)
            m = fmaxf(m, __shfl_xor_sync(0xffffffffu, m, off));
        float e0 = expf(s0 - m), e1 = expf(s1 - m);
        float ssum = e0 + e1;
        #pragma unroll
        for (int off = 16; off > 0; off >>= 1)
            ssum += __shfl_xor_sync(0xffffffffu, ssum, off);
        float inv = 1.f / ssum;
        wg[lane] = e0 * inv;
        wg[lane + 32] = e1 * inv;
    }
    __syncthreads();

    // ---- phase 5: out[bs,f] = sum_l wgt[l] * (Xhi+Xlo)[l,f] ----
    {
        const float* wg = reinterpret_cast<const float*>(smem + WGT_OFF);
        float o = 0.f;
        #pragma unroll 8
        for (int l = 0; l < 64; ++l) {
            float x = __bfloat162float(Xhi[l * XLD + t]) +
                      __bfloat162float(Xlo[l * XLD + t]);
            o = fmaf(wg[l], x, o);
        }
        out[(size_t)bs * Fq + t] = o;
    }
}

extern "C" void kernel_launch(void* const* d_in, const int* in_sizes, int n_in,
                              void* d_out, int out_size)
{
    const float* features = (const float*)d_in[0];
    const float* src_locs = (const float*)d_in[1];
    const float* tar_locs = (const float*)d_in[2];
    const float* W1       = (const float*)d_in[3];
    const float* b1       = (const float*)d_in[4];
    const float* W2       = (const float*)d_in[5];
    const float* b2       = (const float*)d_in[6];
    float* out            = (float*)d_out;

    stage_w1_kernel<<<256, 256>>>(W1);

    cudaFuncSetAttribute(ida_wmma_kernel,
                         cudaFuncAttributeMaxDynamicSharedMemorySize, SMEM_BYTES);
    ida_wmma_kernel<<<Bq * Sq, 256, SMEM_BYTES>>>(
        features, src_locs, tar_locs, b1, W2, b2, out);
}

// round 8
// speedup vs baseline: 2.0255x; 1.2779x over previous
#include <cuda_runtime.h>
#include <cuda_bf16.h>
#include <cstdint>

#define Bq 32
#define Sq 48
#define Lq 64
#define Fq 256

// ---------------- staged W1 in mma.sync B-fragment layout ----------------
// g_Wf[((s*2+comp)*16 + nbp)*32 + lane] : uint4 = {b0,b1 of nblock 2*nbp, b0,b1 of 2*nbp+1}
// b0 = pack(W[s*16+q*2][col], W[s*16+q*2+1][col]), b1 = same +8 k; col = nb*8 + (lane>>2)
__device__ __align__(16) uint4 g_Wf[16 * 2 * 16 * 32];   // 256KB

__device__ __forceinline__ uint32_t pack_bf(float lo, float hi) {
    return ((uint32_t)__bfloat16_as_ushort(__float2bfloat16_rn(hi)) << 16) |
           __bfloat16_as_ushort(__float2bfloat16_rn(lo));
}

__global__ void stage_w1_kernel(const float* __restrict__ W1) {
    int idx = blockIdx.x * 256 + threadIdx.x;   // 16384 uint4s
    int lane = idx & 31;
    int nbp  = (idx >> 5) & 15;
    int comp = (idx >> 9) & 1;
    int s    = idx >> 10;
    int g = lane >> 2, q = lane & 3;
    int k0 = s * 16 + q * 2;
    uint4 r;
    uint32_t* rr = reinterpret_cast<uint32_t*>(&r);
    #pragma unroll
    for (int h = 0; h < 2; ++h) {
        int col = (nbp * 2 + h) * 8 + g;
        float v00 = W1[(k0 + 0) * 256 + col];
        float v01 = W1[(k0 + 1) * 256 + col];
        float v10 = W1[(k0 + 8) * 256 + col];
        float v11 = W1[(k0 + 9) * 256 + col];
        if (comp) {   // lo residual
            v00 -= __bfloat162float(__float2bfloat16_rn(v00));
            v01 -= __bfloat162float(__float2bfloat16_rn(v01));
            v10 -= __bfloat162float(__float2bfloat16_rn(v10));
            v11 -= __bfloat162float(__float2bfloat16_rn(v11));
        }
        rr[h * 2 + 0] = pack_bf(v00, v01);
        rr[h * 2 + 1] = pack_bf(v10, v11);
    }
    g_Wf[idx] = r;
}

// ---------------- helpers ----------------
__device__ __forceinline__ uint32_t smem_u32(const void* p) {
    uint32_t a;
    asm("{ .reg .u64 t; cvta.to.shared.u64 t, %1; cvt.u32.u64 %0, t; }" : "=r"(a) : "l"(p));
    return a;
}
__device__ __forceinline__ void cp16(uint32_t dst, const void* src) {
    asm volatile("cp.async.ca.shared.global [%0], [%1], 16;" :: "r"(dst), "l"(src));
}
#define CP_COMMIT() asm volatile("cp.async.commit_group;" ::: "memory")
#define CP_WAIT0()  asm volatile("cp.async.wait_group 0;" ::: "memory")

__device__ __forceinline__ void mma16816(float* c, const uint4& a, uint32_t b0, uint32_t b1) {
    asm volatile(
        "mma.sync.aligned.m16n8k16.row.col.f32.bf16.bf16.f32 "
        "{%0,%1,%2,%3},{%4,%5,%6,%7},{%8,%9},{%0,%1,%2,%3};"
        : "+f"(c[0]), "+f"(c[1]), "+f"(c[2]), "+f"(c[3])
        : "r"(a.x), "r"(a.y), "r"(a.z), "r"(a.w), "r"(b0), "r"(b1));
}

// ---------------- SMEM layout (bytes) ----------------
// Xf: A-fragment layout [s 16][comp 2][mtg 4][lane 32] uint4 = 64KB
static constexpr int XF_OFF  = 0;
static constexpr int WB_OFF  = 65536;     // 2 stages x 16KB
static constexpr int PRED_OFF = 98304;    // float[256]
static constexpr int W2B1_OFF = 99328;    // float2[256]
static constexpr int INVD_OFF = 101376;   // float[64]
static constexpr int SC_OFF   = 101632;   // float[64]
static constexpr int WGT_OFF  = 101888;   // float[64]
static constexpr int SMEM_BYTES = 102144;

__global__ __launch_bounds__(256, 2)
void ida_mma_kernel(const float* __restrict__ features,
                    const float* __restrict__ src_locs,
                    const float* __restrict__ tar_locs,
                    const float* __restrict__ b1,
                    const float* __restrict__ W2,
                    const float* __restrict__ b2,
                    float* __restrict__ out)
{
    extern __shared__ char smem[];
    const uint32_t sb = smem_u32(smem);
    const int t      = threadIdx.x;
    const int lane   = t & 31;
    const int wid    = t >> 5;
    const int warp_m = wid & 1;        // rows [warp_m*32, +32)
    const int warp_n = wid >> 1;       // cols [warp_n*64, +64)
    const int g      = lane >> 2;
    const int q      = lane & 3;
    const int bs     = blockIdx.x;
    const int b      = bs / Sq;

    // ---- prologue: cp.async W step 0 into stage 0 ----
    {
        #pragma unroll
        for (int j = 0; j < 4; ++j) {
            int seg = t + j * 256;
            cp16(sb + WB_OFF + seg * 16, g_Wf + seg);
        }
        CP_COMMIT();
    }

    // ---- convert X (64x256 f32) into A-fragment layout, hi + lo ----
    {
        const float4* gx = reinterpret_cast<const float4*>(features + (size_t)bs * (Lq * Fq));
        #pragma unroll
        for (int r = 0; r < 16; ++r) {
            int idx = t + r * 256;          // float4 index = m*64 + qq
            int m = idx >> 6, qq = idx & 63;
            float4 x = gx[idx];
            int s     = qq >> 2;
            int colk4 = qq & 3;
            int mtg   = m >> 4;
            int half  = (m >> 3) & 1;
            int regIdx = ((colk4 >> 1) << 1) + half;       // 0..3
            int lane0  = (m & 7) * 4 + (colk4 & 1) * 2;
            uint32_t base_h = sb + XF_OFF + ((((s * 2 + 0) * 4 + mtg) * 32) + lane0) * 16 + regIdx * 4;
            uint32_t base_l = base_h + 4 * 32 * 16;        // comp stride = 4 mtg * 32 lanes * 16B
            float hx = __bfloat162float(__float2bfloat16_rn(x.x));
            float hy = __bfloat162float(__float2bfloat16_rn(x.y));
            float hz = __bfloat162float(__float2bfloat16_rn(x.z));
            float hw = __bfloat162float(__float2bfloat16_rn(x.w));
            uint32_t h0 = pack_bf(x.x, x.y);
            uint32_t h1 = pack_bf(x.z, x.w);
            uint32_t l0 = pack_bf(x.x - hx, x.y - hy);
            uint32_t l1 = pack_bf(x.z - hz, x.w - hw);
            *reinterpret_cast<uint32_t*>(smem + (base_h - sb))      = h0;
            *reinterpret_cast<uint32_t*>(smem + (base_h - sb) + 16) = h1;   // lane0+1
            *reinterpret_cast<uint32_t*>(smem + (base_l - sb))      = l0;
            *reinterpret_cast<uint32_t*>(smem + (base_l - sb) + 16) = l1;
        }
    }
    // aux
    {
        float2* wb = reinterpret_cast<float2*>(smem + W2B1_OFF);
        wb[t] = make_float2(b1[t], W2[t]);
        if (t < Lq) {
            float dx = src_locs[(b * Lq + t) * 2 + 0] - tar_locs[b * 2 + 0];
            float dy = src_locs[(b * Lq + t) * 2 + 1] - tar_locs[b * 2 + 1];
            reinterpret_cast<float*>(smem + INVD_OFF)[t] = rsqrtf(dx * dx + dy * dy);
        }
    }
    CP_WAIT0();
    __syncthreads();

    // ---- mainloop: 16 K-steps, raw mma.sync, pre-formatted fragments ----
    float acc[2][8][4];
    #pragma unroll
    for (int mt = 0; mt < 2; ++mt)
        #pragma unroll
        for (int nt = 0; nt < 8; ++nt)
            #pragma unroll
            for (int k = 0; k < 4; ++k) acc[mt][nt][k] = 0.f;

    #pragma unroll 1
    for (int s = 0; s < 16; ++s) {
        if (s < 15) {
            uint32_t dstb = sb + WB_OFF + ((s + 1) & 1) * 16384;
            const uint4* srcb = g_Wf + (s + 1) * 1024;
            #pragma unroll
            for (int j = 0; j < 4; ++j) {
                int seg = t + j * 256;
                cp16(dstb + seg * 16, srcb + seg);
            }
            CP_COMMIT();
        }

        const char* stage = smem + WB_OFF + (s & 1) * 16384;
        const char* xf    = smem + XF_OFF + (s * 2) * (4 * 32 * 16);

        // A fragments (hi, lo) for this warp's 2 m-tiles
        uint4 Ah[2], Al[2];
        #pragma unroll
        for (int mt = 0; mt < 2; ++mt) {
            int mtg = warp_m * 2 + mt;
            Ah[mt] = *reinterpret_cast<const uint4*>(xf + (mtg * 32 + lane) * 16);
            Al[mt] = *reinterpret_cast<const uint4*>(xf + ((4 + mtg) * 32 + lane) * 16);
        }
        // B hi fragments: 4 x LDS.128 -> 8 n8-frags
        uint4 Bh[4];
        #pragma unroll
        for (int i = 0; i < 4; ++i)
            Bh[i] = *reinterpret_cast<const uint4*>(
                stage + ((warp_n * 4 + i) * 32 + lane) * 16);
        #pragma unroll
        for (int i = 0; i < 4; ++i) {
            mma16816(acc[0][i * 2 + 0], Ah[0], Bh[i].x, Bh[i].y);
            mma16816(acc[1][i * 2 + 0], Ah[1], Bh[i].x, Bh[i].y);
            mma16816(acc[0][i * 2 + 1], Ah[0], Bh[i].z, Bh[i].w);
            mma16816(acc[1][i * 2 + 1], Ah[1], Bh[i].z, Bh[i].w);
            mma16816(acc[0][i * 2 + 0], Al[0], Bh[i].x, Bh[i].y);
            mma16816(acc[1][i * 2 + 0], Al[1], Bh[i].x, Bh[i].y);
            mma16816(acc[0][i * 2 + 1], Al[0], Bh[i].z, Bh[i].w);
            mma16816(acc[1][i * 2 + 1], Al[1], Bh[i].z, Bh[i].w);
        }
        // B lo fragments (reuse regs)
        #pragma unroll
        for (int i = 0; i < 4; ++i)
            Bh[i] = *reinterpret_cast<const uint4*>(
                stage + ((16 * 32) + (warp_n * 4 + i) * 32 + lane) * 16);
        #pragma unroll
        for (int i = 0; i < 4; ++i) {
            mma16816(acc[0][i * 2 + 0], Ah[0], Bh[i].x, Bh[i].y);
            mma16816(acc[1][i * 2 + 0], Ah[1], Bh[i].x, Bh[i].y);
            mma16816(acc[0][i * 2 + 1], Ah[0], Bh[i].z, Bh[i].w);
            mma16816(acc[1][i * 2 + 1], Ah[1], Bh[i].z, Bh[i].w);
        }
        if (s < 15) { CP_WAIT0(); }
        __syncthreads();
    }

    // ---- register epilogue: p = sum_col relu(D+b1)*W2, quad-reduce, store pred ----
    {
        const float2* wb = reinterpret_cast<const float2*>(smem + W2B1_OFF);
        float* pred = reinterpret_cast<float*>(smem + PRED_OFF);
        #pragma unroll
        for (int mt = 0; mt < 2; ++mt) {
            float p0 = 0.f, p1 = 0.f;
            #pragma unroll
            for (int nt = 0; nt < 8; ++nt) {
                int col0 = warp_n * 64 + nt * 8 + q * 2;
                float2 c0 = wb[col0];
                float2 c1 = wb[col0 + 1];
                const float* c = acc[mt][nt];
                p0 = fmaf(fmaxf(c[0] + c0.x, 0.f), c0.y, p0);
                p0 = fmaf(fmaxf(c[1] + c1.x, 0.f), c1.y, p0);
                p1 = fmaf(fmaxf(c[2] + c0.x, 0.f), c0.y, p1);
                p1 = fmaf(fmaxf(c[3] + c1.x, 0.f), c1.y, p1);
            }
            #pragma unroll
            for (int off = 1; off < 4; off <<= 1) {
                p0 += __shfl_xor_sync(0xffffffffu, p0, off);
                p1 += __shfl_xor_sync(0xffffffffu, p1, off);
            }
            if (q == 0) {
                int row = warp_m * 32 + mt * 16 + g;
                pred[warp_n * 64 + row]     = p0;
                pred[warp_n * 64 + row + 8] = p1;
            }
        }
    }
    __syncthreads();
    {
        const float* pred = reinterpret_cast<const float*>(smem + PRED_OFF);
        if (t < 64) {
            float ptot = pred[t] + pred[t + 64] + pred[t + 128] + pred[t + 192];
            float sscore = fmaxf(ptot + b2[0], 0.f) *
                           reinterpret_cast<const float*>(smem + INVD_OFF)[t];
            reinterpret_cast<float*>(smem + SC_OFF)[t] = sscore;
        }
    }
    __syncthreads();

    // ---- softmax over L=64 (warp 0) ----
    if (wid == 0) {
        const float* sc = reinterpret_cast<const float*>(smem + SC_OFF);
        float* wg = reinterpret_cast<float*>(smem + WGT_OFF);
        float s0 = sc[lane], s1 = sc[lane + 32];
        float m = fmaxf(s0, s1);
        #pragma unroll
        for (int off = 16; off > 0; off >>= 1)
            m = fmaxf(m, __shfl_xor_sync(0xffffffffu, m, off));
        float e0 = expf(s0 - m), e1 = expf(s1 - m);
        float ssum = e0 + e1;
        #pragma unroll
        for (int off = 16; off > 0; off >>= 1)
            ssum += __shfl_xor_sync(0xffffffffu, ssum, off);
        float inv = 1.f / ssum;
        wg[lane] = e0 * inv;
        wg[lane + 32] = e1 * inv;
    }
    __syncthreads();

    // ---- phase 5: out[bs,f] = sum_l wgt[l] * features[bs,l,f]  (L2-hot, fp32) ----
    {
        const float* wg = reinterpret_cast<const float*>(smem + WGT_OFF);
        const float* fx = features + (size_t)bs * (Lq * Fq);
        float o = 0.f;
        #pragma unroll 8
        for (int l = 0; l < 64; ++l)
            o = fmaf(wg[l], fx[l * Fq + t], o);
        out[(size_t)bs * Fq + t] = o;
    }
}

extern "C" void kernel_launch(void* const* d_in, const int* in_sizes, int n_in,
                              void* d_out, int out_size)
{
    const float* features = (const float*)d_in[0];
    const float* src_locs = (const float*)d_in[1];
    const float* tar_locs = (const float*)d_in[2];
    const float* W1       = (const float*)d_in[3];
    const float* b1       = (const float*)d_in[4];
    const float* W2       = (const float*)d_in[5];
    const float* b2       = (const float*)d_in[6];
    float* out            = (float*)d_out;

    stage_w1_kernel<<<64, 256>>>(W1);

    cudaFuncSetAttribute(ida_mma_kernel,
                         cudaFuncAttributeMaxDynamicSharedMemorySize, SMEM_BYTES);
    ida_mma_kernel<<<Bq * Sq, 256, SMEM_BYTES>>>(
        features, src_locs, tar_locs, b1, W2, b2, out);
}